// round 3
// baseline (speedup 1.0000x reference)
#include <cuda_runtime.h>
#include <cuda_bf16.h>
#include <stdint.h>

// Problem constants
#define T_LEN   262144
#define A_DIM   64
#define ALPHA_F 0.99f
#define GAMMA_F 0.999f
#define LAMBD_F 0.7f

#define CHUNK   1024
#define NCHUNK  (T_LEN / CHUNK)   // 256

// ---------------- scratch (__device__ globals, no allocation) ----------------
__device__ float g_vpq[T_LEN];        // pi_t . q_t
__device__ float g_vpt[T_LEN + 1];    // pi_t . q_tar_t   (need indices 1..T)
__device__ float g_qta[T_LEN];        // q[t, a_t]
__device__ float g_rho[T_LEN];        // pi[t,a]/mu[t,a]
__device__ float g_eb [T_LEN];        // est + ALPHA*(q_t_a - v_t)
__device__ float g_Aex[T_LEN];        // exclusive suffix composite A
__device__ float g_Bex[T_LEN];        // exclusive suffix composite B
__device__ float g_cA [NCHUNK];
__device__ float g_cB [NCHUNK];
__device__ float g_carry[NCHUNK];

__device__ __forceinline__ float sel4(const float4 v, int c) {
    // c in [0,3], uniform within a 16-lane half
    float r = v.x;
    if (c == 1) r = v.y;
    else if (c == 2) r = v.z;
    else if (c == 3) r = v.w;
    return r;
}

// ---------------- K1: per-row reductions + advantages ----------------
// 16 lanes per row (float4 per lane), 2 rows per warp. Rows 0..T inclusive.
__global__ void k1_rows(const float* __restrict__ q,
                        const float* __restrict__ q_tar,
                        const float* __restrict__ pi,
                        const float* __restrict__ mu,
                        const int*   __restrict__ a_t,
                        float* __restrict__ adv_out)   // = d_out + T_LEN
{
    const int warp = blockIdx.x * (blockDim.x >> 5) + (threadIdx.x >> 5);
    const int lane = threadIdx.x & 31;
    const int half = lane >> 4;            // 0 or 1
    const int sub  = lane & 15;            // lane within half
    const int row  = warp * 2 + half;      // rows 0 .. T_LEN inclusive
    if (row > T_LEN) return;
    const unsigned hm = 0xFFFFu << (half << 4);   // per-half shuffle mask

    const size_t base = (size_t)row * A_DIM;
    const float4 qv = __ldg(((const float4*)(q     + base)) + sub);
    const float4 pv = __ldg(((const float4*)(pi    + base)) + sub);
    const float4 tv = __ldg(((const float4*)(q_tar + base)) + sub);

    float s1 = pv.x * qv.x + pv.y * qv.y + pv.z * qv.z + pv.w * qv.w; // pi.q
    float s2 = pv.x * tv.x + pv.y * tv.y + pv.z * tv.z + pv.w * tv.w; // pi.q_tar
    #pragma unroll
    for (int o = 8; o; o >>= 1) {
        s1 += __shfl_xor_sync(hm, s1, o);
        s2 += __shfl_xor_sync(hm, s2, o);
    }

    if (row < T_LEN) {
        const float v = s1;
        const float coef = 1.0f - ALPHA_F;     // 0.01
        float4 adv;
        adv.x = coef * (qv.x - v);
        adv.y = coef * (qv.y - v);
        adv.z = coef * (qv.z - v);
        adv.w = coef * (qv.w - v);
        ((float4*)(adv_out + base))[sub] = adv;

        const int a = __ldg(a_t + row);        // uniform within the half
        const int comp = a & 3;
        const int src  = (half << 4) + (a >> 2);
        float qcand = sel4(qv, comp);
        float pcand = sel4(pv, comp);
        float qa = __shfl_sync(hm, qcand, src);
        float pa = __shfl_sync(hm, pcand, src);
        if (sub == 0) {
            g_vpq[row] = s1;
            g_qta[row] = qa;
            g_rho[row] = pa / __ldg(mu + base + a);
        }
    }
    if (sub == 0) g_vpt[row] = s2;
}

// ---------------- K2: per-element coeffs + per-chunk suffix scan ----------------
// Chunk = block of 1024 threads. Affine f_t(y) = a*y + b; inclusive suffix
// composite S_i = f_i o ... o f_end; stores exclusive composite and chunk summary.
__global__ void k2_scan(const float* __restrict__ r_t,
                        const int*   __restrict__ done_t)
{
    const int tid = threadIdx.x;
    const int t   = blockIdx.x * CHUNK + tid;

    const int   d   = __ldg(done_t + t);
    const float est = __ldg(r_t + t) + (d ? 0.0f : GAMMA_F) * g_vpt[t + 1];
    const float qa  = g_qta[t];
    const float rho = g_rho[t];
    const float td  = est - qa;
    const float c   = LAMBD_F * fminf(fmaxf(rho, 0.0f), 1.0f);

    float a = d ? 0.0f : (GAMMA_F * c);
    const float lg = (float)(0.7 * 0.999);      // LAMBD*GAMMA (double -> f32)
    float b = lg * rho * td;

    g_eb[t] = est + ALPHA_F * (qa - g_vpq[t]);

    __shared__ float sA[CHUNK];
    __shared__ float sB[CHUNK];
    sA[tid] = a; sB[tid] = b;
    __syncthreads();

    // Hillis-Steele inclusive suffix scan; combine(L,R) = (aL*aR, aL*bR + bL)
    #pragma unroll
    for (int off = 1; off < CHUNK; off <<= 1) {
        float la = sA[tid], lb = sB[tid];
        float ra = 1.0f, rb = 0.0f;
        bool valid = (tid + off) < CHUNK;
        if (valid) { ra = sA[tid + off]; rb = sB[tid + off]; }
        __syncthreads();
        if (valid) { sA[tid] = la * ra; sB[tid] = la * rb + lb; }
        __syncthreads();
    }

    float Ae = (tid == CHUNK - 1) ? 1.0f : sA[tid + 1];
    float Be = (tid == CHUNK - 1) ? 0.0f : sB[tid + 1];
    g_Aex[t] = Ae;
    g_Bex[t] = Be;
    if (tid == 0) {
        g_cA[blockIdx.x] = sA[0];
        g_cB[blockIdx.x] = sB[0];
    }
}

// ---------------- K3: serial compose chunk summaries (reverse) ----------------
__global__ void k3_chunks()
{
    if (threadIdx.x == 0 && blockIdx.x == 0) {
        float carry = 0.0f;
        for (int k = NCHUNK - 1; k >= 0; --k) {
            g_carry[k] = carry;                      // carry entering chunk k
            carry = g_cA[k] * carry + g_cB[k];       // exit of chunk k
        }
    }
}

// ---------------- K4: apply carries, write targets_q ----------------
__global__ void k4_apply(const int* __restrict__ done_t,
                         float* __restrict__ targets)
{
    int t = blockIdx.x * blockDim.x + threadIdx.x;
    if (t >= T_LEN) return;
    float carry = g_carry[t >> 10];
    float y_in  = g_Aex[t] * carry + g_Bex[t];
    float z     = __ldg(done_t + t) ? 0.0f : y_in;
    targets[t]  = g_eb[t] + z;
}

// ---------------- launch ----------------
extern "C" void kernel_launch(void* const* d_in, const int* in_sizes, int n_in,
                              void* d_out, int out_size)
{
    const float* q     = (const float*)d_in[0];   // (T+1, 64)
    const float* q_tar = (const float*)d_in[1];   // (T+1, 64)
    const float* pi    = (const float*)d_in[2];   // (T+1, 64)
    const int*   a_t   = (const int*)  d_in[3];   // (T,)
    const float* r_t   = (const float*)d_in[4];   // (T,)
    const float* mu_t  = (const float*)d_in[5];   // (T, 64)
    const int*   done  = (const int*)  d_in[6];   // (T,)

    float* out_targets = (float*)d_out;           // first T floats
    float* out_adv     = (float*)d_out + T_LEN;   // then T*64 floats

    // K1: 2 rows per warp, 8 warps per 256-thread block, rows = T+1
    {
        int rows  = T_LEN + 1;
        int warps = (rows + 1) / 2;
        int warps_per_blk = 8;
        int blocks = (warps + warps_per_blk - 1) / warps_per_blk;
        k1_rows<<<blocks, 256>>>(q, q_tar, pi, mu_t, a_t, out_adv);
    }
    // K2: 256 chunks of 1024
    k2_scan<<<NCHUNK, CHUNK>>>(r_t, done);
    // K3: serial chunk compose
    k3_chunks<<<1, 32>>>();
    // K4: elementwise targets
    k4_apply<<<T_LEN / 256, 256>>>(done, out_targets);
}

// round 10
// speedup vs baseline: 1.1600x; 1.1600x over previous
#include <cuda_runtime.h>
#include <cuda_bf16.h>
#include <stdint.h>

// Problem constants
#define T_LEN   262144
#define A_DIM   64
#define ALPHA_F 0.99f
#define GAMMA_F 0.999f
#define LAMBD_F 0.7f

#define CHUNK   1024
#define NCHUNK  (T_LEN / CHUNK)   // 256
#define K2_THREADS 256
#define ITEMS   4                 // K2_THREADS * ITEMS == CHUNK

#define INCL_MARKER 0xACEACE01u

// ---------------- scratch (__device__ globals, no allocation) ----------------
__device__ float g_vpq [T_LEN];     // pi_t . q_t
__device__ float g_vpts[T_LEN];     // pi_{t+1} . q_tar_{t+1}  (SHIFTED: index t holds vpt[t+1])
__device__ float g_qta [T_LEN];     // q[t, a_t]
__device__ float g_rho [T_LEN];     // pi[t,a]/mu[t,a]
__device__ unsigned long long g_agg [NCHUNK];  // packed (A,B) chunk aggregate
__device__ unsigned long long g_incl[NCHUNK];  // packed (marker, y_out)
__device__ int   g_flag[NCHUNK];               // 0 = none, 1 = aggregate published

// combine(L, R) = L o R  (R applied to carry first):  a = aL*aR ; b = aL*bR + bL
__device__ __forceinline__ void comb(float& la, float& lb, float ra, float rb) {
    lb = fmaf(la, rb, lb);
    la = la * ra;
}

__device__ __forceinline__ float sel4(const float4 v, int c) {
    float r = v.x;
    if (c == 1) r = v.y;
    else if (c == 2) r = v.z;
    else if (c == 3) r = v.w;
    return r;
}

// ---------------- K1: per-row reductions + advantages ----------------
// 16 lanes per row (float4 per lane), 2 rows per warp. Rows 0..T inclusive.
// Block 0 also resets the lookback state for this launch (ordered before K2).
__global__ void k1_rows(const float* __restrict__ q,
                        const float* __restrict__ q_tar,
                        const float* __restrict__ pi,
                        const float* __restrict__ mu,
                        const int*   __restrict__ a_t,
                        float* __restrict__ adv_out)   // = d_out + T_LEN
{
    if (blockIdx.x == 0 && threadIdx.x < NCHUNK) {   // K2_THREADS==NCHUNK==256
        g_flag[threadIdx.x] = 0;
        g_incl[threadIdx.x] = 0ull;
    }

    const int warp = blockIdx.x * (blockDim.x >> 5) + (threadIdx.x >> 5);
    const int lane = threadIdx.x & 31;
    const int half = lane >> 4;            // 0 or 1
    const int sub  = lane & 15;            // lane within half
    const int row  = warp * 2 + half;      // rows 0 .. T_LEN inclusive
    if (row > T_LEN) return;
    const unsigned hm = 0xFFFFu << (half << 4);   // per-half shuffle mask

    const size_t base = (size_t)row * A_DIM;
    const float4 qv = __ldg(((const float4*)(q     + base)) + sub);
    const float4 pv = __ldg(((const float4*)(pi    + base)) + sub);
    const float4 tv = __ldg(((const float4*)(q_tar + base)) + sub);

    float s1 = pv.x * qv.x + pv.y * qv.y + pv.z * qv.z + pv.w * qv.w; // pi.q
    float s2 = pv.x * tv.x + pv.y * tv.y + pv.z * tv.z + pv.w * tv.w; // pi.q_tar
    #pragma unroll
    for (int o = 8; o; o >>= 1) {
        s1 += __shfl_xor_sync(hm, s1, o);
        s2 += __shfl_xor_sync(hm, s2, o);
    }

    if (row < T_LEN) {
        const float v = s1;
        const float coef = 1.0f - ALPHA_F;     // 0.01
        float4 adv;
        adv.x = coef * (qv.x - v);
        adv.y = coef * (qv.y - v);
        adv.z = coef * (qv.z - v);
        adv.w = coef * (qv.w - v);
        ((float4*)(adv_out + base))[sub] = adv;

        const int a = __ldg(a_t + row);        // uniform within the half
        const int comp = a & 3;
        const int src  = (half << 4) + (a >> 2);
        float qcand = sel4(qv, comp);
        float pcand = sel4(pv, comp);
        float qa = __shfl_sync(hm, qcand, src);
        float pa = __shfl_sync(hm, pcand, src);
        if (sub == 0) {
            g_vpq[row] = s1;
            g_qta[row] = qa;
            g_rho[row] = pa / __ldg(mu + base + a);
        }
    }
    if (sub == 0 && row > 0) g_vpts[row - 1] = s2;   // shifted store: vpts[t] = vpt[t+1]
}

// in-lane-order warp composite reduce: result (lane 0) = L0 o L1 o ... o L31
__device__ __forceinline__ void warp_reduce_ordered(float& ra, float& rb, int lane) {
    #pragma unroll
    for (int off = 1; off < 32; off <<= 1) {
        float oa = __shfl_down_sync(0xffffffffu, ra, off);
        float ob = __shfl_down_sync(0xffffffffu, rb, off);
        if (lane + off < 32) comb(ra, rb, oa, ob);
    }
}

// ---------------- K2: fused coeffs + suffix scan (decoupled lookback) + targets ----
// Block b handles chunk c = NCHUNK-1-b (so lookback waits only on LOWER block ids).
// All 256 blocks (8 warps each) are co-resident -> spin-wait is deadlock-free.
// Lookback is WARP-PARALLEL (32 predecessors per window) to kill the serial tail.
__global__ void __launch_bounds__(K2_THREADS, 4)
k2_fused(const float* __restrict__ r_t,
         const int*   __restrict__ done_t,
         float* __restrict__ targets)
{
    const int b    = blockIdx.x;
    const int c    = NCHUNK - 1 - b;
    const int tid  = threadIdx.x;
    const int lane = tid & 31;
    const int w    = tid >> 5;
    const int base = c * CHUNK + tid * ITEMS;

    const int4   dn = __ldg((const int4*)  (done_t + base));
    const float4 rv = __ldg((const float4*)(r_t    + base));
    const float4 vp = *(const float4*)(g_vpts + base);
    const float4 qa = *(const float4*)(g_qta  + base);
    const float4 rh = *(const float4*)(g_rho  + base);
    const float4 vq = *(const float4*)(g_vpq  + base);

    const int   dArr[4]  = {dn.x, dn.y, dn.z, dn.w};
    const float rArr[4]  = {rv.x, rv.y, rv.z, rv.w};
    const float vpArr[4] = {vp.x, vp.y, vp.z, vp.w};
    const float qaArr[4] = {qa.x, qa.y, qa.z, qa.w};
    const float rhArr[4] = {rh.x, rh.y, rh.z, rh.w};
    const float vqArr[4] = {vq.x, vq.y, vq.z, vq.w};

    const float lg = (float)(0.7 * 0.999);   // LAMBD*GAMMA (python double -> f32)

    float aA[4], aB[4], eb[4];
    #pragma unroll
    for (int i = 0; i < 4; i++) {
        const int   d   = dArr[i];
        const float est = rArr[i] + (d ? 0.0f : GAMMA_F) * vpArr[i];
        const float td  = est - qaArr[i];
        const float cc  = LAMBD_F * fminf(fmaxf(rhArr[i], 0.0f), 1.0f);
        aA[i] = d ? 0.0f : (GAMMA_F * cc);
        aB[i] = lg * rhArr[i] * td;
        eb[i] = est + ALPHA_F * (qaArr[i] - vqArr[i]);
    }

    // per-element exclusive suffix composites within the thread (element 3 = latest t)
    float xa[4], xb[4];
    xa[3] = 1.0f;  xb[3] = 0.0f;
    xa[2] = aA[3]; xb[2] = aB[3];
    xa[1] = aA[2]; xb[1] = aB[2]; comb(xa[1], xb[1], xa[2], xb[2]);
    xa[0] = aA[1]; xb[0] = aB[1]; comb(xa[0], xb[0], xa[1], xb[1]);
    float ta = aA[0], tb = aB[0]; comb(ta, tb, xa[0], xb[0]);   // thread composite

    // warp inclusive suffix scan of thread composites (higher lane = later t)
    float ia = ta, ib = tb;
    #pragma unroll
    for (int off = 1; off < 32; off <<= 1) {
        float oa = __shfl_down_sync(0xffffffffu, ia, off);
        float ob = __shfl_down_sync(0xffffffffu, ib, off);
        if (lane + off < 32) comb(ia, ib, oa, ob);
    }
    // exclusive per-lane
    float ea  = __shfl_down_sync(0xffffffffu, ia, 1);
    float ebx = __shfl_down_sync(0xffffffffu, ib, 1);
    if (lane == 31) { ea = 1.0f; ebx = 0.0f; }

    __shared__ float swa[8], swb[8];
    __shared__ float s_carry;
    if (lane == 0) { swa[w] = ia; swb[w] = ib; }   // warp composite = lane 0 inclusive
    __syncthreads();

    // exclusive suffix over warps: EW_w = W_{w+1} o ... o W_7
    float wa = 1.0f, wb = 0.0f;
    #pragma unroll
    for (int j = 7; j >= 1; j--) {
        if (j > w) {
            float na = swa[j], nb = swb[j];
            comb(na, nb, wa, wb);    // acc = W_j o acc
            wa = na; wb = nb;
        }
    }

    // full exclusive-within-chunk per element: X_i = e_i o E_lane o EW_w
    float fa = ea, fb = ebx;
    comb(fa, fb, wa, wb);
    #pragma unroll
    for (int i = 0; i < 4; i++) comb(xa[i], xb[i], fa, fb);

    // ---- warp 0: publish aggregate, warp-parallel lookback, publish inclusive ----
    if (w == 0) {
        // block aggregate, uniform across warp 0
        float Ba = __shfl_sync(0xffffffffu, ia, 0);
        float Bb = __shfl_sync(0xffffffffu, ib, 0);
        comb(Ba, Bb, wa, wb);   // wa,wb uniform within warp 0

        if (lane == 0) {
            unsigned long long pk =
                ((unsigned long long)__float_as_uint(Ba) << 32) | __float_as_uint(Bb);
            atomicExch(&g_agg[b], pk);
            __threadfence();
            atomicExch(&g_flag[b], 1);
        }

        float carry = 0.0f;
        if (b > 0) {
            float acc_a = 1.0f, acc_b = 0.0f;   // composite of consumed whole windows
            int base_p = b - 1;
            for (;;) {
                const int p = base_p - lane;
                int st; float va, vb;
                if (p < 0) { st = 2; va = 0.0f; vb = 0.0f; }   // boundary: inclusive y=0
                else {
                    unsigned long long iv = atomicAdd(&g_incl[p], 0ull);
                    if ((unsigned)(iv >> 32) == INCL_MARKER) {
                        st = 2; va = 0.0f; vb = __uint_as_float((unsigned)iv);
                    } else if (atomicAdd(&g_flag[p], 0) != 0) {
                        __threadfence();
                        unsigned long long av = atomicAdd(&g_agg[p], 0ull);
                        st = 1;
                        va = __uint_as_float((unsigned)(av >> 32));
                        vb = __uint_as_float((unsigned)av);
                    } else {
                        st = 0; va = 1.0f; vb = 0.0f;   // identity placeholder
                    }
                }
                const unsigned m_incl = __ballot_sync(0xffffffffu, st == 2);
                const unsigned m_nr   = __ballot_sync(0xffffffffu, st == 0);
                if (m_incl != 0) {
                    const int lstar = __ffs(m_incl) - 1;
                    const unsigned below = (lstar == 0) ? 0u : ((1u << lstar) - 1u);
                    if ((m_nr & below) == 0) {
                        // in-order composite; (0,y) at lstar right-absorbs later lanes
                        warp_reduce_ordered(va, vb, lane);
                        float Wb = __shfl_sync(0xffffffffu, vb, 0);
                        carry = fmaf(acc_a, Wb, acc_b);
                        break;
                    }
                } else if (m_nr == 0) {
                    // full window of aggregates: fold and advance 32 back
                    warp_reduce_ordered(va, vb, lane);
                    float Wa = __shfl_sync(0xffffffffu, va, 0);
                    float Wb = __shfl_sync(0xffffffffu, vb, 0);
                    comb(acc_a, acc_b, Wa, Wb);
                    base_p -= 32;
                    continue;
                }
                __nanosleep(20);   // retry this window
            }
        }

        if (lane == 0) {
            float y_out = fmaf(Ba, carry, Bb);
            unsigned long long ipk =
                ((unsigned long long)INCL_MARKER << 32) | __float_as_uint(y_out);
            __threadfence();
            atomicExch(&g_incl[b], ipk);
            s_carry = carry;
        }
    }
    __syncthreads();

    const float carry = s_carry;
    float4 o;
    {
        float y0 = fmaf(xa[0], carry, xb[0]);
        float y1 = fmaf(xa[1], carry, xb[1]);
        float y2 = fmaf(xa[2], carry, xb[2]);
        float y3 = fmaf(xa[3], carry, xb[3]);
        o.x = eb[0] + (dArr[0] ? 0.0f : y0);
        o.y = eb[1] + (dArr[1] ? 0.0f : y1);
        o.z = eb[2] + (dArr[2] ? 0.0f : y2);
        o.w = eb[3] + (dArr[3] ? 0.0f : y3);
    }
    *(float4*)(targets + base) = o;
}

// ---------------- launch ----------------
extern "C" void kernel_launch(void* const* d_in, const int* in_sizes, int n_in,
                              void* d_out, int out_size)
{
    const float* q     = (const float*)d_in[0];   // (T+1, 64)
    const float* q_tar = (const float*)d_in[1];   // (T+1, 64)
    const float* pi    = (const float*)d_in[2];   // (T+1, 64)
    const int*   a_t   = (const int*)  d_in[3];   // (T,)
    const float* r_t   = (const float*)d_in[4];   // (T,)
    const float* mu_t  = (const float*)d_in[5];   // (T, 64)
    const int*   done  = (const int*)  d_in[6];   // (T,)

    float* out_targets = (float*)d_out;           // first T floats
    float* out_adv     = (float*)d_out + T_LEN;   // then T*64 floats

    // K1: 2 rows per warp, 8 warps per 256-thread block, rows = T+1
    {
        int rows  = T_LEN + 1;
        int warps = (rows + 1) / 2;
        int warps_per_blk = 8;
        int blocks = (warps + warps_per_blk - 1) / warps_per_blk;
        k1_rows<<<blocks, 256>>>(q, q_tar, pi, mu_t, a_t, out_adv);
    }
    // K2: fused scan + targets, single pass with warp-parallel decoupled lookback
    k2_fused<<<NCHUNK, K2_THREADS>>>(r_t, done, out_targets);
}

// round 11
// speedup vs baseline: 1.2897x; 1.1119x over previous
#include <cuda_runtime.h>
#include <cuda_bf16.h>
#include <stdint.h>

// Problem constants
#define T_LEN   262144
#define A_DIM   64
#define ALPHA_F 0.99f
#define GAMMA_F 0.999f
#define LAMBD_F 0.7f

// Windowed scan: decay a_t <= gamma*lambda = 0.6993, so any suffix composite
// over >= 512 elements has A == +0 exactly in f32 (underflow), killing the
// inter-chunk carry. Each block scans a 1024 window, outputs the first 512.
#define OUT   512
#define WIN   1024
#define NWIN  (T_LEN / OUT)    // 512 blocks
#define ITEMS 4                // 256 threads * 4 = 1024 window

// ---------------- scratch (__device__ globals, no allocation) ----------------
__device__ float g_vpq [T_LEN];     // pi_t . q_t
__device__ float g_vpts[T_LEN];     // pi_{t+1} . q_tar_{t+1}  (SHIFTED: index t holds vpt[t+1])
__device__ float g_qta [T_LEN];     // q[t, a_t]
__device__ float g_rho [T_LEN];     // pi[t,a]/mu[t,a]

// combine(L, R) = L o R  (R applied to carry first):  a = aL*aR ; b = aL*bR + bL
__device__ __forceinline__ void comb(float& la, float& lb, float ra, float rb) {
    lb = fmaf(la, rb, lb);
    la = la * ra;
}

__device__ __forceinline__ float sel4(const float4 v, int c) {
    float r = v.x;
    if (c == 1) r = v.y;
    else if (c == 2) r = v.z;
    else if (c == 3) r = v.w;
    return r;
}

// ---------------- K1: per-row reductions + advantages ----------------
// 16 lanes per row (float4 per lane), 2 rows per warp. Rows 0..T inclusive.
__global__ void k1_rows(const float* __restrict__ q,
                        const float* __restrict__ q_tar,
                        const float* __restrict__ pi,
                        const float* __restrict__ mu,
                        const int*   __restrict__ a_t,
                        float* __restrict__ adv_out)   // = d_out + T_LEN
{
    const int warp = blockIdx.x * (blockDim.x >> 5) + (threadIdx.x >> 5);
    const int lane = threadIdx.x & 31;
    const int half = lane >> 4;            // 0 or 1
    const int sub  = lane & 15;            // lane within half
    const int row  = warp * 2 + half;      // rows 0 .. T_LEN inclusive
    if (row > T_LEN) return;
    const unsigned hm = 0xFFFFu << (half << 4);   // per-half shuffle mask

    const size_t base = (size_t)row * A_DIM;
    const float4 qv = __ldg(((const float4*)(q     + base)) + sub);
    const float4 pv = __ldg(((const float4*)(pi    + base)) + sub);
    const float4 tv = __ldg(((const float4*)(q_tar + base)) + sub);

    float s1 = pv.x * qv.x + pv.y * qv.y + pv.z * qv.z + pv.w * qv.w; // pi.q
    float s2 = pv.x * tv.x + pv.y * tv.y + pv.z * tv.z + pv.w * tv.w; // pi.q_tar
    #pragma unroll
    for (int o = 8; o; o >>= 1) {
        s1 += __shfl_xor_sync(hm, s1, o);
        s2 += __shfl_xor_sync(hm, s2, o);
    }

    if (row < T_LEN) {
        const float v = s1;
        const float coef = 1.0f - ALPHA_F;     // 0.01
        float4 adv;
        adv.x = coef * (qv.x - v);
        adv.y = coef * (qv.y - v);
        adv.z = coef * (qv.z - v);
        adv.w = coef * (qv.w - v);
        ((float4*)(adv_out + base))[sub] = adv;

        const int a = __ldg(a_t + row);        // uniform within the half
        const int comp = a & 3;
        const int src  = (half << 4) + (a >> 2);
        float qcand = sel4(qv, comp);
        float pcand = sel4(pv, comp);
        float qa = __shfl_sync(hm, qcand, src);
        float pa = __shfl_sync(hm, pcand, src);
        if (sub == 0) {
            g_vpq[row] = s1;
            g_qta[row] = qa;
            g_rho[row] = pa / __ldg(mu + base + a);
        }
    }
    if (sub == 0 && row > 0) g_vpts[row - 1] = s2;   // shifted store: vpts[t] = vpt[t+1]
}

// ---------------- K2: windowed suffix scan, fully parallel -------------------
// Block B: window [B*OUT, B*OUT+WIN), outputs [B*OUT, B*OUT+OUT).
// Every output has >= 512 in-window future elements -> suffix A underflows to
// exactly 0 -> y_in = X_b with no carry. Last block reaches true sequence end
// (carry = 0 exactly). No atomics, no inter-block communication.
__global__ void __launch_bounds__(256)
k2_win(const float* __restrict__ r_t,
       const int*   __restrict__ done_t,
       float* __restrict__ targets)
{
    const int tid  = threadIdx.x;
    const int lane = tid & 31;
    const int w    = tid >> 5;
    const int W    = blockIdx.x * OUT;          // window start
    const int gbase = W + tid * ITEMS;          // this thread's 4 elements
    const bool valid = (gbase + ITEMS - 1) < T_LEN;   // quad-aligned; all-or-none

    const float lg = (float)(0.7 * 0.999);      // LAMBD*GAMMA (python double -> f32)

    float aA[4], aB[4], eb[4];
    int   dArr[4];
    if (valid) {
        const int4   dn = __ldg((const int4*)  (done_t + gbase));
        const float4 rv = __ldg((const float4*)(r_t    + gbase));
        const float4 vp = *(const float4*)(g_vpts + gbase);
        const float4 qa = *(const float4*)(g_qta  + gbase);
        const float4 rh = *(const float4*)(g_rho  + gbase);

        const float rArr[4]  = {rv.x, rv.y, rv.z, rv.w};
        const float vpArr[4] = {vp.x, vp.y, vp.z, vp.w};
        const float qaArr[4] = {qa.x, qa.y, qa.z, qa.w};
        const float rhArr[4] = {rh.x, rh.y, rh.z, rh.w};
        dArr[0] = dn.x; dArr[1] = dn.y; dArr[2] = dn.z; dArr[3] = dn.w;

        #pragma unroll
        for (int i = 0; i < 4; i++) {
            const int   d   = dArr[i];
            const float est = rArr[i] + (d ? 0.0f : GAMMA_F) * vpArr[i];
            const float td  = est - qaArr[i];
            const float cc  = LAMBD_F * fminf(fmaxf(rhArr[i], 0.0f), 1.0f);
            aA[i] = d ? 0.0f : (GAMMA_F * cc);
            aB[i] = lg * rhArr[i] * td;
            eb[i] = est;   // + ALPHA*(qa - vpq) added below for output warps
        }
        if (w < 4) {       // only output warps need vpq
            const float4 vq = *(const float4*)(g_vpq + gbase);
            eb[0] += ALPHA_F * (qaArr[0] - vq.x);
            eb[1] += ALPHA_F * (qaArr[1] - vq.y);
            eb[2] += ALPHA_F * (qaArr[2] - vq.z);
            eb[3] += ALPHA_F * (qaArr[3] - vq.w);
        }
    } else {
        #pragma unroll
        for (int i = 0; i < 4; i++) { aA[i] = 1.0f; aB[i] = 0.0f; eb[i] = 0.0f; dArr[i] = 0; }
    }

    // per-element exclusive suffix composites within the thread (element 3 = latest t)
    float xa[4], xb[4];
    xa[3] = 1.0f;  xb[3] = 0.0f;
    xa[2] = aA[3]; xb[2] = aB[3];
    xa[1] = aA[2]; xb[1] = aB[2]; comb(xa[1], xb[1], xa[2], xb[2]);
    xa[0] = aA[1]; xb[0] = aB[1]; comb(xa[0], xb[0], xa[1], xb[1]);
    float ta = aA[0], tb = aB[0]; comb(ta, tb, xa[0], xb[0]);   // thread composite

    // warp inclusive suffix scan of thread composites (higher lane = later t)
    float ia = ta, ib = tb;
    #pragma unroll
    for (int off = 1; off < 32; off <<= 1) {
        float oa = __shfl_down_sync(0xffffffffu, ia, off);
        float ob = __shfl_down_sync(0xffffffffu, ib, off);
        if (lane + off < 32) comb(ia, ib, oa, ob);
    }
    // exclusive per-lane
    float ea  = __shfl_down_sync(0xffffffffu, ia, 1);
    float ebx = __shfl_down_sync(0xffffffffu, ib, 1);
    if (lane == 31) { ea = 1.0f; ebx = 0.0f; }

    __shared__ float swa[8], swb[8];
    if (lane == 0) { swa[w] = ia; swb[w] = ib; }   // warp composite = lane 0 inclusive
    __syncthreads();

    // exclusive suffix over warps: EW_w = W_{w+1} o ... o W_7
    float wa = 1.0f, wb = 0.0f;
    #pragma unroll
    for (int j = 7; j >= 1; j--) {
        if (j > w) {
            float na = swa[j], nb = swb[j];
            comb(na, nb, wa, wb);    // acc = W_j o acc
            wa = na; wb = nb;
        }
    }

    if (w < 4) {   // output region: elements [W, W+512)
        // full exclusive-within-window per element: X_i = e_i o E_lane o EW_w
        float fa = ea, fb = ebx;
        comb(fa, fb, wa, wb);
        #pragma unroll
        for (int i = 0; i < 4; i++) comb(xa[i], xb[i], fa, fb);

        // carry beyond window is annihilated (Xa == +0 exactly): y_in = Xb
        float4 o;
        o.x = eb[0] + (dArr[0] ? 0.0f : xb[0]);
        o.y = eb[1] + (dArr[1] ? 0.0f : xb[1]);
        o.z = eb[2] + (dArr[2] ? 0.0f : xb[2]);
        o.w = eb[3] + (dArr[3] ? 0.0f : xb[3]);
        *(float4*)(targets + gbase) = o;
    }
}

// ---------------- launch ----------------
extern "C" void kernel_launch(void* const* d_in, const int* in_sizes, int n_in,
                              void* d_out, int out_size)
{
    const float* q     = (const float*)d_in[0];   // (T+1, 64)
    const float* q_tar = (const float*)d_in[1];   // (T+1, 64)
    const float* pi    = (const float*)d_in[2];   // (T+1, 64)
    const int*   a_t   = (const int*)  d_in[3];   // (T,)
    const float* r_t   = (const float*)d_in[4];   // (T,)
    const float* mu_t  = (const float*)d_in[5];   // (T, 64)
    const int*   done  = (const int*)  d_in[6];   // (T,)

    float* out_targets = (float*)d_out;           // first T floats
    float* out_adv     = (float*)d_out + T_LEN;   // then T*64 floats

    // K1: 2 rows per warp, 8 warps per 256-thread block, rows = T+1
    {
        int rows  = T_LEN + 1;
        int warps = (rows + 1) / 2;
        int warps_per_blk = 8;
        int blocks = (warps + warps_per_blk - 1) / warps_per_blk;
        k1_rows<<<blocks, 256>>>(q, q_tar, pi, mu_t, a_t, out_adv);
    }
    // K2: fully parallel windowed scan (decay kills inter-window carry exactly)
    k2_win<<<NWIN, 256>>>(r_t, done, out_targets);
}

// round 15
// speedup vs baseline: 1.3945x; 1.0813x over previous
#include <cuda_runtime.h>
#include <cuda_bf16.h>
#include <stdint.h>

// Problem constants
#define T_LEN   262144
#define A_DIM   64
#define ALPHA_F 0.99f
#define GAMMA_F 0.999f
#define LAMBD_F 0.7f

// Windowed scan: decay a_t <= gamma*lambda = 0.6993, so any suffix composite
// over >= 512 elements has A == +0 exactly in f32 (underflow: 0.6993^289 < 2^-149),
// killing the inter-chunk carry. Block scans 1024 window, outputs first 512.
#define OUT   512
#define WIN   1024
#define NWIN  (T_LEN / OUT)    // 512 blocks
#define ITEMS 4                // 256 threads * 4 = 1024 window

// ---------------- scratch (__device__ globals, no allocation) ----------------
__device__ float g_vpq [T_LEN];     // pi_t . q_t
__device__ float g_vpts[T_LEN];     // pi_{t+1} . q_tar_{t+1}  (SHIFTED: index t holds vpt[t+1])
__device__ float g_qta [T_LEN];     // q[t, a_t]
__device__ float g_rho [T_LEN];     // pi[t,a]/mu[t,a]

// combine(L, R) = L o R  (R applied to carry first):  a = aL*aR ; b = aL*bR + bL
__device__ __forceinline__ void comb(float& la, float& lb, float ra, float rb) {
    lb = fmaf(la, rb, lb);
    la = la * ra;
}

__device__ __forceinline__ float sel4(const float4 v, int c) {
    float r = v.x;
    if (c == 1) r = v.y;
    else if (c == 2) r = v.z;
    else if (c == 3) r = v.w;
    return r;
}

// ---------------- K1: per-row reductions + advantages ----------------
// 16 lanes per row (float4 per lane), 2 rows per warp. Rows 0..T inclusive.
// a_t and mu loads hoisted BEFORE the reduction to overlap their ~1100cyc
// serial latency with the shuffle tree.
__global__ void k1_rows(const float* __restrict__ q,
                        const float* __restrict__ q_tar,
                        const float* __restrict__ pi,
                        const float* __restrict__ mu,
                        const int*   __restrict__ a_t,
                        float* __restrict__ adv_out)   // = d_out + T_LEN
{
    const int warp = blockIdx.x * (blockDim.x >> 5) + (threadIdx.x >> 5);
    const int lane = threadIdx.x & 31;
    const int half = lane >> 4;            // 0 or 1
    const int sub  = lane & 15;            // lane within half
    const int row  = warp * 2 + half;      // rows 0 .. T_LEN inclusive
    if (row > T_LEN) {
        cudaTriggerProgrammaticLaunchCompletion();
        return;
    }
    const unsigned hm = 0xFFFFu << (half << 4);   // per-half shuffle mask
    const bool inner = (row < T_LEN);

    // issue action load first (independent of everything)
    int a = 0;
    if (inner) a = __ldg(a_t + row);

    const size_t base = (size_t)row * A_DIM;
    const float4 qv = __ldg(((const float4*)(q     + base)) + sub);
    const float4 pv = __ldg(((const float4*)(pi    + base)) + sub);
    const float4 tv = __ldg(((const float4*)(q_tar + base)) + sub);

    // mu load depends only on `a` — issue before reduction so it overlaps
    float muv = 1.0f;
    if (inner) muv = __ldg(mu + base + a);

    float s1 = pv.x * qv.x + pv.y * qv.y + pv.z * qv.z + pv.w * qv.w; // pi.q
    float s2 = pv.x * tv.x + pv.y * tv.y + pv.z * tv.z + pv.w * tv.w; // pi.q_tar
    #pragma unroll
    for (int o = 8; o; o >>= 1) {
        s1 += __shfl_xor_sync(hm, s1, o);
        s2 += __shfl_xor_sync(hm, s2, o);
    }

    if (inner) {
        const float v = s1;
        const float coef = 1.0f - ALPHA_F;     // 0.01
        float4 adv;
        adv.x = coef * (qv.x - v);
        adv.y = coef * (qv.y - v);
        adv.z = coef * (qv.z - v);
        adv.w = coef * (qv.w - v);
        ((float4*)(adv_out + base))[sub] = adv;

        const int comp = a & 3;                // a uniform within the half
        const int src  = (half << 4) + (a >> 2);
        float qcand = sel4(qv, comp);
        float pcand = sel4(pv, comp);
        float qa = __shfl_sync(hm, qcand, src);
        float pa = __shfl_sync(hm, pcand, src);
        if (sub == 0) {
            g_vpq[row] = s1;
            g_qta[row] = qa;
            g_rho[row] = pa / muv;
        }
    }
    if (sub == 0 && row > 0) g_vpts[row - 1] = s2;   // shifted store: vpts[t] = vpt[t+1]

    // PDL: all our global writes are done; let the dependent grid's sync release.
    cudaTriggerProgrammaticLaunchCompletion();
}

// ---------------- K2: windowed suffix scan, fully parallel -------------------
// Block B: window [B*OUT, B*OUT+WIN), outputs [B*OUT, B*OUT+OUT).
// PDL: launched programmatically; loads K1-independent inputs (r_t, done_t)
// BEFORE cudaGridDependencySynchronize so they overlap K1's tail.
__global__ void __launch_bounds__(256)
k2_win(const float* __restrict__ r_t,
       const int*   __restrict__ done_t,
       float* __restrict__ targets)
{
    const int tid  = threadIdx.x;
    const int lane = tid & 31;
    const int w    = tid >> 5;
    const int W    = blockIdx.x * OUT;          // window start
    const int gbase = W + tid * ITEMS;          // this thread's 4 elements
    const bool valid = (gbase + ITEMS - 1) < T_LEN;   // quad-aligned; all-or-none

    const float lg = (float)(0.7 * 0.999);      // LAMBD*GAMMA (python double -> f32)

    // ---- pre-sync: K1-independent loads overlap K1 execution ----
    int4   dn = make_int4(0, 0, 0, 0);
    float4 rv = make_float4(0.f, 0.f, 0.f, 0.f);
    if (valid) {
        dn = __ldg((const int4*)  (done_t + gbase));
        rv = __ldg((const float4*)(r_t    + gbase));
    }

    // ---- wait for K1's stores to be visible ----
    cudaGridDependencySynchronize();

    float aA[4], aB[4], eb[4];
    int   dArr[4];
    dArr[0] = dn.x; dArr[1] = dn.y; dArr[2] = dn.z; dArr[3] = dn.w;
    if (valid) {
        const float4 vp = *(const float4*)(g_vpts + gbase);
        const float4 qa = *(const float4*)(g_qta  + gbase);
        const float4 rh = *(const float4*)(g_rho  + gbase);

        const float rArr[4]  = {rv.x, rv.y, rv.z, rv.w};
        const float vpArr[4] = {vp.x, vp.y, vp.z, vp.w};
        const float qaArr[4] = {qa.x, qa.y, qa.z, qa.w};
        const float rhArr[4] = {rh.x, rh.y, rh.z, rh.w};

        #pragma unroll
        for (int i = 0; i < 4; i++) {
            const int   d   = dArr[i];
            const float est = rArr[i] + (d ? 0.0f : GAMMA_F) * vpArr[i];
            const float td  = est - qaArr[i];
            const float cc  = LAMBD_F * fminf(fmaxf(rhArr[i], 0.0f), 1.0f);
            aA[i] = d ? 0.0f : (GAMMA_F * cc);
            aB[i] = lg * rhArr[i] * td;
            eb[i] = est;   // + ALPHA*(qa - vpq) added below for output warps
        }
        if (w < 4) {       // only output warps need vpq
            const float4 vq = *(const float4*)(g_vpq + gbase);
            eb[0] += ALPHA_F * (qaArr[0] - vq.x);
            eb[1] += ALPHA_F * (qaArr[1] - vq.y);
            eb[2] += ALPHA_F * (qaArr[2] - vq.z);
            eb[3] += ALPHA_F * (qaArr[3] - vq.w);
        }
    } else {
        #pragma unroll
        for (int i = 0; i < 4; i++) { aA[i] = 1.0f; aB[i] = 0.0f; eb[i] = 0.0f; dArr[i] = 0; }
    }

    // per-element exclusive suffix composites within the thread (element 3 = latest t)
    float xa[4], xb[4];
    xa[3] = 1.0f;  xb[3] = 0.0f;
    xa[2] = aA[3]; xb[2] = aB[3];
    xa[1] = aA[2]; xb[1] = aB[2]; comb(xa[1], xb[1], xa[2], xb[2]);
    xa[0] = aA[1]; xb[0] = aB[1]; comb(xa[0], xb[0], xa[1], xb[1]);
    float ta = aA[0], tb = aB[0]; comb(ta, tb, xa[0], xb[0]);   // thread composite

    // warp inclusive suffix scan of thread composites (higher lane = later t)
    float ia = ta, ib = tb;
    #pragma unroll
    for (int off = 1; off < 32; off <<= 1) {
        float oa = __shfl_down_sync(0xffffffffu, ia, off);
        float ob = __shfl_down_sync(0xffffffffu, ib, off);
        if (lane + off < 32) comb(ia, ib, oa, ob);
    }
    // exclusive per-lane
    float ea  = __shfl_down_sync(0xffffffffu, ia, 1);
    float ebx = __shfl_down_sync(0xffffffffu, ib, 1);
    if (lane == 31) { ea = 1.0f; ebx = 0.0f; }

    __shared__ float swa[8], swb[8];
    if (lane == 0) { swa[w] = ia; swb[w] = ib; }   // warp composite = lane 0 inclusive
    __syncthreads();

    // exclusive suffix over warps: EW_w = W_{w+1} o ... o W_7
    float wa = 1.0f, wb = 0.0f;
    #pragma unroll
    for (int j = 7; j >= 1; j--) {
        if (j > w) {
            float na = swa[j], nb = swb[j];
            comb(na, nb, wa, wb);    // acc = W_j o acc
            wa = na; wb = nb;
        }
    }

    if (w < 4) {   // output region: elements [W, W+512)
        // full exclusive-within-window per element: X_i = e_i o E_lane o EW_w
        float fa = ea, fb = ebx;
        comb(fa, fb, wa, wb);
        #pragma unroll
        for (int i = 0; i < 4; i++) comb(xa[i], xb[i], fa, fb);

        // carry beyond window is annihilated (Xa == +0 exactly): y_in = Xb
        float4 o;
        o.x = eb[0] + (dArr[0] ? 0.0f : xb[0]);
        o.y = eb[1] + (dArr[1] ? 0.0f : xb[1]);
        o.z = eb[2] + (dArr[2] ? 0.0f : xb[2]);
        o.w = eb[3] + (dArr[3] ? 0.0f : xb[3]);
        *(float4*)(targets + gbase) = o;
    }
}

// ---------------- launch ----------------
extern "C" void kernel_launch(void* const* d_in, const int* in_sizes, int n_in,
                              void* d_out, int out_size)
{
    const float* q     = (const float*)d_in[0];   // (T+1, 64)
    const float* q_tar = (const float*)d_in[1];   // (T+1, 64)
    const float* pi    = (const float*)d_in[2];   // (T+1, 64)
    const int*   a_t   = (const int*)  d_in[3];   // (T,)
    const float* r_t   = (const float*)d_in[4];   // (T,)
    const float* mu_t  = (const float*)d_in[5];   // (T, 64)
    const int*   done  = (const int*)  d_in[6];   // (T,)

    float* out_targets = (float*)d_out;           // first T floats
    float* out_adv     = (float*)d_out + T_LEN;   // then T*64 floats

    // K1: 2 rows per warp, 8 warps per 256-thread block, rows = T+1
    {
        int rows  = T_LEN + 1;
        int warps = (rows + 1) / 2;
        int warps_per_blk = 8;
        int blocks = (warps + warps_per_blk - 1) / warps_per_blk;
        k1_rows<<<blocks, 256>>>(q, q_tar, pi, mu_t, a_t, out_adv);
    }
    // K2: PDL launch — overlaps its prologue (r_t/done_t loads) with K1's tail.
    {
        cudaLaunchAttribute attr[1];
        attr[0].id = cudaLaunchAttributeProgrammaticStreamSerialization;
        attr[0].val.programmaticStreamSerializationAllowed = 1;

        cudaLaunchConfig_t cfg = {};
        cfg.gridDim  = dim3(NWIN);
        cfg.blockDim = dim3(256);
        cfg.dynamicSmemBytes = 0;
        cfg.stream = 0;
        cfg.attrs = attr;
        cfg.numAttrs = 1;
        cudaLaunchKernelEx(&cfg, k2_win, r_t, done, out_targets);
    }
}